// round 15
// baseline (speedup 1.0000x reference)
#include <cuda_runtime.h>
#include <cuda_bf16.h>

// FM_12060268167845: factorization machine forward.
//   d_in[0] idx  i32 [B,K], d_in[1] x f32 [B,K], d_in[2] b f32 [B,K],
//   d_in[3] w f32 [1M,1], d_in[4] V f32 [1M,128], d_in[5] bias f32 [1]
// out f32 [B] = sigmoid(bias + Xw + 0.5/sum(x) * sum_f((XV)^2 - X2V2))
//
// v14 = v13 (dual per-row sorted streams, batch-interleaved U=10, __ldcg;
// traffic at the ~453MB compulsory floor) with SM load balancing:
// grid = 1036 = 148*7 CTAs -> exactly 7 CTAs on every SM (v13's 1024 left
// ~24 SMs with 6 CTAs; they idled the last ~14% while 7-CTA SMs finished,
// costing ~7% of DRAM utilization). 4096 row-pair tasks are assigned
// task = warp*1036 + blockIdx.x so the 48 surplus warp-slots spread one
// per CTA across 48 distinct SMs (residual imbalance 3.6%).

#define FM_B 8192
#define FM_K 200
#define FM_F 128
#define WARPS 4
#define THREADS (WARPS * 32)
#define NBLOCKS 1036               // 148 SMs * 7 CTAs
#define NTASKS (FM_B / 2)          // 4096 row-pairs
#define U 10                       // FM_K % U == 0 (20 batches per row)
#define NBIN 8
#define BIN_SHIFT 26               // 64MB slices of the 512MB V table
#define CHUNKS 7                   // ceil(200/32)

__global__ __launch_bounds__(THREADS, 7)
void fm_kernel(const int* __restrict__ idx,
               const float* __restrict__ x_vals,
               const float* __restrict__ b_vals,
               const float* __restrict__ w,
               const float* __restrict__ V,
               const float* __restrict__ bias,
               float* __restrict__ out)
{
    const int warp = threadIdx.x >> 5;
    const int lane = threadIdx.x & 31;
    const unsigned lt_mask = (1u << lane) - 1u;

    __shared__ unsigned s_off[WARPS][2][FM_K];
    __shared__ float    s_x[WARPS][2][FM_K];
    __shared__ float    s_scal[WARPS][4];     // xwA, sxA, xwB, sxB

    // Task assignment: spreads idle slots one-per-CTA across distinct SMs.
    const int task = warp * NBLOCKS + blockIdx.x;
    if (task >= NTASKS) return;
    const int bA = task * 2;                  // rows bA, bA+1

    // ---- per-row: stage + ballot bin-sort ----
    for (int r = 0; r < 2; ++r) {
        const int base = (bA + r) * FM_K;

        unsigned eoff[CHUNKS];
        float    ex[CHUNKS];
        float xw = 0.0f, sx = 0.0f;
        #pragma unroll
        for (int c = 0; c < CHUNKS; ++c) {
            int k = c * 32 + lane;
            if (k < FM_K) {
                int   id = idx[base + k];
                float xv = x_vals[base + k];
                eoff[c] = (unsigned)id * (FM_F * 4u);    // id * 512 bytes
                ex[c]   = xv;
                sx += xv;
                xw = fmaf(b_vals[base + k], __ldg(&w[id]), xw);
            } else {
                eoff[c] = 0xFFFFFFFFu;                   // sentinel: no bin
                ex[c]   = 0.0f;
            }
        }

        #pragma unroll
        for (int o = 16; o > 0; o >>= 1) {
            xw += __shfl_down_sync(0xffffffffu, xw, o);
            sx += __shfl_down_sync(0xffffffffu, sx, o);
        }
        if (lane == 0) {
            s_scal[warp][2 * r + 0] = xw;
            s_scal[warp][2 * r + 1] = sx;
        }

        int cnt[NBIN];
        #pragma unroll
        for (int bb = 0; bb < NBIN; ++bb) cnt[bb] = 0;
        #pragma unroll
        for (int c = 0; c < CHUNKS; ++c) {
            unsigned bin = eoff[c] >> BIN_SHIFT;
            #pragma unroll
            for (int bb = 0; bb < NBIN; ++bb)
                cnt[bb] += __popc(__ballot_sync(0xffffffffu, bin == (unsigned)bb));
        }
        int run[NBIN];
        {
            int acc = 0;
            #pragma unroll
            for (int bb = 0; bb < NBIN; ++bb) { run[bb] = acc; acc += cnt[bb]; }
        }
        #pragma unroll
        for (int c = 0; c < CHUNKS; ++c) {
            unsigned bin = eoff[c] >> BIN_SHIFT;
            #pragma unroll
            for (int bb = 0; bb < NBIN; ++bb) {
                unsigned msk = __ballot_sync(0xffffffffu, bin == (unsigned)bb);
                if (bin == (unsigned)bb) {
                    int pos = run[bb] + __popc(msk & lt_mask);
                    s_off[warp][r][pos] = eoff[c];
                    s_x[warp][r][pos]   = ex[c];
                }
                run[bb] += __popc(msk);
            }
        }
    }
    __syncwarp();

    // ---- batch-interleaved dense mainloop (A batch, then B batch) ----
    const char* __restrict__ Vb = (const char*)V;
    const unsigned lane_off = (unsigned)lane << 4;
    const unsigned* __restrict__ offA = s_off[warp][0];
    const unsigned* __restrict__ offB = s_off[warp][1];
    const float*    __restrict__ xA   = s_x[warp][0];
    const float*    __restrict__ xB   = s_x[warp][1];

    float4 a1A = make_float4(0.f, 0.f, 0.f, 0.f);
    float4 a1B = make_float4(0.f, 0.f, 0.f, 0.f);
    float  a2A = 0.0f, a2B = 0.0f;

    for (int k0 = 0; k0 < FM_K; k0 += U) {
        {   // --- row A batch ---
            float4 v[U];
            #pragma unroll
            for (int u = 0; u < U; ++u)
                v[u] = __ldcg((const float4*)(Vb + offA[k0 + u] + lane_off));
            #pragma unroll
            for (int u = 0; u < U; ++u) {
                float x  = xA[k0 + u];
                float x2 = x * x;
                a1A.x = fmaf(x, v[u].x, a1A.x);
                a1A.y = fmaf(x, v[u].y, a1A.y);
                a1A.z = fmaf(x, v[u].z, a1A.z);
                a1A.w = fmaf(x, v[u].w, a1A.w);
                float n2 = fmaf(v[u].x, v[u].x,
                           fmaf(v[u].y, v[u].y,
                           fmaf(v[u].z, v[u].z, v[u].w * v[u].w)));
                a2A = fmaf(x2, n2, a2A);
            }
        }
        {   // --- row B batch ---
            float4 v[U];
            #pragma unroll
            for (int u = 0; u < U; ++u)
                v[u] = __ldcg((const float4*)(Vb + offB[k0 + u] + lane_off));
            #pragma unroll
            for (int u = 0; u < U; ++u) {
                float x  = xB[k0 + u];
                float x2 = x * x;
                a1B.x = fmaf(x, v[u].x, a1B.x);
                a1B.y = fmaf(x, v[u].y, a1B.y);
                a1B.z = fmaf(x, v[u].z, a1B.z);
                a1B.w = fmaf(x, v[u].w, a1B.w);
                float n2 = fmaf(v[u].x, v[u].x,
                           fmaf(v[u].y, v[u].y,
                           fmaf(v[u].z, v[u].z, v[u].w * v[u].w)));
                a2B = fmaf(x2, n2, a2B);
            }
        }
    }

    // ---- reductions + outputs ----
    float pqA = fmaf(a1A.x, a1A.x,
                fmaf(a1A.y, a1A.y,
                fmaf(a1A.z, a1A.z, a1A.w * a1A.w))) - a2A;
    float pqB = fmaf(a1B.x, a1B.x,
                fmaf(a1B.y, a1B.y,
                fmaf(a1B.z, a1B.z, a1B.w * a1B.w))) - a2B;

    #pragma unroll
    for (int o = 16; o > 0; o >>= 1) {
        pqA += __shfl_down_sync(0xffffffffu, pqA, o);
        pqB += __shfl_down_sync(0xffffffffu, pqB, o);
    }

    if (lane == 0) {
        float bia = bias[0];
        float pA  = 0.5f * (1.0f / s_scal[warp][1]) * pqA;
        out[bA]     = 1.0f / (1.0f + __expf(-(bia + s_scal[warp][0] + pA)));
        float pB  = 0.5f * (1.0f / s_scal[warp][3]) * pqB;
        out[bA + 1] = 1.0f / (1.0f + __expf(-(bia + s_scal[warp][2] + pB)));
    }
}

extern "C" void kernel_launch(void* const* d_in, const int* in_sizes, int n_in,
                              void* d_out, int out_size)
{
    const int*   idx    = (const int*)d_in[0];
    const float* x_vals = (const float*)d_in[1];
    const float* b_vals = (const float*)d_in[2];
    const float* w      = (const float*)d_in[3];
    const float* V      = (const float*)d_in[4];
    const float* bias   = (const float*)d_in[5];
    float*       out    = (float*)d_out;
    (void)in_sizes; (void)n_in; (void)out_size;

    fm_kernel<<<NBLOCKS, THREADS>>>(idx, x_vals, b_vals, w, V, bias, out);
}